// round 16
// baseline (speedup 1.0000x reference)
#include <cuda_runtime.h>
#include <cuda_fp16.h>
#include <cstdint>

// Problem constants
#define B      8
#define C_IN   16
#define H      128
#define W      128
#define KSIZE  3
#define HO     126
#define WO     126
#define NK     128

#define TILE_X 32
#define TILE_Y 16
#define NTHREADS 512

// Weights fp16, layout [k][t][c]: half index = k*152 + t*16 + c
#define WKH     152
#define W_TOTAL_H (NK * WKH)                 // 19456 halves
#define W_BYTES   (W_TOTAL_H * 2)            // 38912

// Data records fp16 in smem: [p][c], p = ry*DIN_X+rx, record 32 B, stride 48 B
#define DIN_Y   (TILE_Y + KSIZE - 1)         // 18
#define DIN_X   (TILE_X + KSIZE - 1)         // 34
#define NREC    (DIN_Y * DIN_X)              // 612
#define RECSTR  48
#define D_BYTES (NREC * RECSTR)              // 29376
#define D_OFF   W_BYTES

#define SMEM_BYTES (W_BYTES + D_BYTES)       // 68288 (2 blocks/SM -> 136.6 KB)

// 256 tile blocks, each also owning 1/256 of the prep. 256 <= 148*2 resident
// slots, so ALL blocks are co-resident in wave 1 -> spin barrier cannot deadlock.
#define NTILE   256
#define W4_PER_BLOCK 18                      // 4608 float4s / 256
#define ROWS_PER_BLOCK 4                     // 1024 (b,h) rows / 256

__device__ __align__(16) __half g_wbuf[W_TOTAL_H];
__device__ __align__(16) __half g_dbuf[B * H * W * C_IN];   // [b][h][w][c]
__device__ int g_done = 0;   // blocks that finished their prep share
__device__ int g_fin  = 0;   // blocks finished entirely (for counter reset)

// ---------- cp.async helpers ----------
__device__ __forceinline__ void cp_async16(unsigned int dst, const void* src) {
    asm volatile("cp.async.cg.shared.global [%0], [%1], 16;\n" :: "r"(dst), "l"(src));
}
__device__ __forceinline__ void cp_async_wait_all() {
    asm volatile("cp.async.commit_group;\n");
    asm volatile("cp.async.wait_group 0;\n" ::: "memory");
}

__global__ __launch_bounds__(NTHREADS, 2)
void kernel_lookup_fused(const float* __restrict__ data,
                         const int* __restrict__ kernel_idx,
                         const float* __restrict__ weights,
                         float* __restrict__ out)
{
    extern __shared__ __align__(16) char smem[];
    const unsigned int smem_u32 = (unsigned int)__cvta_generic_to_shared(smem);
    const int tid = threadIdx.x;
    const int bid = blockIdx.x;                 // 0..255

    // ---------------- prep share (1/256 per block) ----------------
    // weights: 18 float4s -> fp16 scatter into g_wbuf [k][t][c]
    if (tid < W4_PER_BLOCK) {
        int i4 = bid * W4_PER_BLOCK + tid;      // < 4608
        float4 v = reinterpret_cast<const float4*>(weights)[i4];
        int base = i4 * 4;
        #pragma unroll
        for (int u = 0; u < 4; ++u) {
            int e = base + u;
            int k = e / 144;
            int r = e - k * 144;
            int c = r / 9;
            int t = r - c * 9;
            float f = (u == 0) ? v.x : (u == 1) ? v.y : (u == 2) ? v.z : v.w;
            g_wbuf[k * WKH + t * 16 + c] = __float2half_rn(f);
        }
    }
    // data transpose: 4 global rows (b,h); 128 threads per row, thread = one w.
    {
        int rowg = bid * ROWS_PER_BLOCK + (tid >> 7);   // 0..1023
        int w    = tid & 127;
        int db   = rowg >> 7;
        int h    = rowg & 127;
        const float* src = data + ((size_t)(db * C_IN) * H + h) * W + w;
        unsigned hh[8];
        #pragma unroll
        for (int c2 = 0; c2 < 8; ++c2) {
            float f0 = src[(size_t)(2 * c2 + 0) * H * W];
            float f1 = src[(size_t)(2 * c2 + 1) * H * W];
            __half2 p = __floats2half2_rn(f0, f1);
            hh[c2] = *reinterpret_cast<unsigned*>(&p);
        }
        uint4* dst = reinterpret_cast<uint4*>(g_dbuf + ((size_t)(db * H + h) * W + w) * C_IN);
        uint4 q0; q0.x = hh[0]; q0.y = hh[1]; q0.z = hh[2]; q0.w = hh[3];
        uint4 q1; q1.x = hh[4]; q1.y = hh[5]; q1.z = hh[6]; q1.w = hh[7];
        dst[0] = q0;
        dst[1] = q1;
    }
    __syncthreads();
    __threadfence();
    if (tid == 0) atomicAdd(&g_done, 1);

    // ---------------- tile coords + early kidx load ----------------
    const int bx = bid & 3;
    const int by = (bid >> 2) & 7;
    const int b  = bid >> 5;
    const int ty0 = by * TILE_Y;
    const int tx0 = bx * TILE_X;

    const int tx = tid & 31;
    const int ty = tid >> 5;            // 0..15
    const int oy = ty0 + ty;
    const int ox = tx0 + tx;
    const bool valid = (oy < HO) && (ox < WO);

    int k = 0;
    if (valid) k = kernel_idx[((size_t)b * HO + oy) * WO + ox];

    // ---------------- global barrier: all 256 prep shares done ----------------
    // Safe: all 256 blocks are resident (256 <= 296 slots), so every block
    // reaches its atomicAdd regardless of scheduling order.
    if (tid == 0) {
        while (atomicAdd(&g_done, 0) < NTILE) { __nanosleep(64); }
    }
    __syncthreads();

    // ---- stage weights: coalesced 16B async copies (L2 path, no stale L1) ----
    {
        const char* src = reinterpret_cast<const char*>(g_wbuf);
        #pragma unroll 1
        for (int i = tid; i < W_BYTES / 16; i += NTHREADS)       // 2432
            cp_async16(smem_u32 + i * 16, src + i * 16);
    }

    // ---- stage data records: 32B contiguous gmem -> 48B-strided smem ----
    {
        const __half* dimg = g_dbuf + (size_t)b * H * W * C_IN;
        #pragma unroll 1
        for (int p = tid; p < NREC; p += NTHREADS) {             // 612 records
            int ry = p / DIN_X;
            int rx = p - ry * DIN_X;
            int gy = ty0 + ry;
            int gx = tx0 + rx;
            if (gy >= H || gx >= W) continue;   // garbage only feeds invalid px
            const char* src = reinterpret_cast<const char*>(dimg + ((size_t)gy * W + gx) * C_IN);
            unsigned int dst = smem_u32 + D_OFF + p * RECSTR;
            cp_async16(dst,      src);
            cp_async16(dst + 16, src + 16);
        }
    }

    cp_async_wait_all();
    __syncthreads();

    // ---- compute: per tap 2 weight LDS.128 + 2 data LDS.128, CVT+FFMA ----
    const uint4* wq    = reinterpret_cast<const uint4*>(smem + k * (WKH * 2));   // 19 quads/k
    const char*  dbase = smem + D_OFF + (ty * DIN_X + tx) * RECSTR;

    const int doff[9] = { 0*RECSTR, 1*RECSTR, 2*RECSTR,
                          34*RECSTR, 35*RECSTR, 36*RECSTR,
                          68*RECSTR, 69*RECSTR, 70*RECSTR };

    float acc0 = 0.f, acc1 = 0.f, acc2 = 0.f, acc3 = 0.f;

    #pragma unroll
    for (int t = 0; t < 9; ++t) {
        const uint4* dq = reinterpret_cast<const uint4*>(dbase + doff[t]);
        uint4 wA = wq[t * 2];
        uint4 wB = wq[t * 2 + 1];
        uint4 dA = dq[0];
        uint4 dB = dq[1];

        const unsigned* wa = &wA.x;
        const unsigned* da = &dA.x;
        #pragma unroll
        for (int j = 0; j < 4; ++j) {
            float2 wf = __half22float2(*reinterpret_cast<const __half2*>(&wa[j]));
            float2 df = __half22float2(*reinterpret_cast<const __half2*>(&da[j]));
            acc0 = fmaf(wf.x, df.x, acc0);
            acc1 = fmaf(wf.y, df.y, acc1);
        }
        const unsigned* wb = &wB.x;
        const unsigned* db = &dB.x;
        #pragma unroll
        for (int j = 0; j < 4; ++j) {
            float2 wf = __half22float2(*reinterpret_cast<const __half2*>(&wb[j]));
            float2 df = __half22float2(*reinterpret_cast<const __half2*>(&db[j]));
            acc2 = fmaf(wf.x, df.x, acc2);
            acc3 = fmaf(wf.y, df.y, acc3);
        }
    }

    if (valid)
        out[((size_t)b * HO + oy) * WO + ox] = (acc0 + acc1) + (acc2 + acc3);

    // counter reset for graph replays: last block zeroes both counters.
    if (tid == 0) {
        int r = atomicAdd(&g_fin, 1);
        if (r == NTILE - 1) {
            atomicExch(&g_fin, 0);
            atomicExch(&g_done, 0);
        }
    }
}

extern "C" void kernel_launch(void* const* d_in, const int* in_sizes, int n_in,
                              void* d_out, int out_size)
{
    const float* data = (const float*)d_in[0];
    const int*   kidx = (const int*)d_in[1];
    const float* wts  = (const float*)d_in[2];
    float*       outp = (float*)d_out;

    cudaFuncSetAttribute(kernel_lookup_fused,
                         cudaFuncAttributeMaxDynamicSharedMemorySize,
                         SMEM_BYTES);
    kernel_lookup_fused<<<NTILE, NTHREADS, SMEM_BYTES>>>(data, kidx, wts, outp);
}